// round 7
// baseline (speedup 1.0000x reference)
#include <cuda_runtime.h>
#include <math.h>

#define BS 2
#define SN 512
#define W 64
#define MODES 16
#define PAIRS ((SN*(SN-1))/2)
#define GRID 296
#define NTHR 256

// ---------------- scratch (device globals; no allocation) ----------------
__device__ float g_h [BS*W*SN];
__device__ float g_hT[BS*SN*W];
__device__ float g_a [BS*W*SN];
__device__ float g_aT[BS*SN*W];
__device__ float g_p [BS*W*SN];
__device__ float g_pT[BS*SN*W];
__device__ float g_ux[BS*SN*SN];   // exp(-|p_i - p_j|)
__device__ float g_vr[BS*SN*SN];   // |a_i - a_j|
__device__ float g_Xf[BS*W*MODES*2];
__device__ float g_Mx[BS*SN*8*W];  // dense masked-sum partials (8 i-chunks)
__device__ float g_Mv[BS*SN*8*W];
__device__ float g_R [BS*SN*W];    // vecs-projection sums
__device__ int   g_N [BS*SN];      // partner counts
__device__ int   g_vrmax[4*BS];
__device__ float g_cos[SN*MODES];
__device__ float g_sin[SN*MODES];

// ---------------- grid-wide barrier (busy spin) ----------------
__device__ int          g_count = 0;
__device__ volatile int g_gen   = 0;

__device__ __forceinline__ void gbar() {
    __syncthreads();
    if (threadIdx.x == 0) {
        __threadfence();
        int my = g_gen;
        if (atomicAdd(&g_count, 1) == GRID - 1) {
            g_count = 0;
            __threadfence();
            g_gen = my + 1;
        } else {
            while (g_gen == my) { }
        }
        __threadfence();
    }
    __syncthreads();
}

// ---- 64x64 distance tile via SYRK trick: d^2 = nI + nJ - 2*dot ----
template<int MODE>   // 0: dst = exp(-d) ; 1: dst = d, track per-(l,b) max
__device__ __forceinline__ void dist_tile(const float* __restrict__ src,
                                          float* __restrict__ dst,
                                          int b, int tile, float* sb, int l) {
    float* sI = sb;
    float* sJ = sb + 4096;
    float* nI = sb + 8192;
    float* nJ = sb + 8256;
    int* smax = (int*)(sb + 8320);
    const int tid = threadIdx.x;
    const int I0 = (tile >> 3) << 6, J0 = (tile & 7) << 6;

    for (int e = tid; e < 1024; e += NTHR) {
        int c = e >> 4, q = e & 15;
        ((float4*)sI)[c*16 + q] = *(const float4*)(src + (b*W + c)*SN + I0 + q*4);
        ((float4*)sJ)[c*16 + q] = *(const float4*)(src + (b*W + c)*SN + J0 + q*4);
    }
    if (MODE == 1 && tid == 0) *smax = 0;
    __syncthreads();
    if (tid < 64) {
        float s = 0.f;
        #pragma unroll 16
        for (int c = 0; c < W; c++) { float v = sI[c*64 + tid]; s += v*v; }
        nI[tid] = s;
    } else if (tid < 128) {
        int t = tid - 64;
        float s = 0.f;
        #pragma unroll 16
        for (int c = 0; c < W; c++) { float v = sJ[c*64 + t]; s += v*v; }
        nJ[t] = s;
    }
    __syncthreads();

    const int tx = tid & 15, ty = tid >> 4;
    float acc[4][4] = {};
    #pragma unroll 4
    for (int c = 0; c < W; c++) {
        float4 ri = *(const float4*)(sI + c*64 + ty*4);
        float4 rj = *(const float4*)(sJ + c*64 + tx*4);
        float riv[4] = {ri.x, ri.y, ri.z, ri.w};
        float rjv[4] = {rj.x, rj.y, rj.z, rj.w};
        #pragma unroll
        for (int r = 0; r < 4; r++)
            #pragma unroll
            for (int s = 0; s < 4; s++)
                acc[r][s] += riv[r] * rjv[s];
    }

    float vmax = 0.f;
    #pragma unroll
    for (int r = 0; r < 4; r++) {
        int row = ty*4 + r;
        float nr = nI[row];
        float4 o;
        float ov[4];
        #pragma unroll
        for (int s = 0; s < 4; s++) {
            float d2 = nr + nJ[tx*4 + s] - 2.f*acc[r][s];
            float d = sqrtf(fmaxf(d2, 0.f));
            if (MODE == 0) ov[s] = expf(-d);
            else { ov[s] = d; vmax = fmaxf(vmax, d); }
        }
        o.x = ov[0]; o.y = ov[1]; o.z = ov[2]; o.w = ov[3];
        *(float4*)(dst + ((size_t)b*SN + I0 + row)*SN + J0 + tx*4) = o;
    }
    if (MODE == 1) {
        #pragma unroll
        for (int o2 = 16; o2; o2 >>= 1)
            vmax = fmaxf(vmax, __shfl_down_sync(0xffffffffu, vmax, o2));
        if ((tid & 31) == 0) atomicMax(smax, __float_as_int(vmax));
        __syncthreads();
        if (tid == 0) atomicMax(&g_vrmax[l*BS + b], *smax);
    }
    __syncthreads();
}

extern "C" __global__ void __launch_bounds__(NTHR, 2)
mega(const float* __restrict__ x, const float* __restrict__ vecs,
     const float* __restrict__ fc0_w, const float* __restrict__ fc0_b,
     const float* __restrict__ spec_w, const float* __restrict__ conv_w,
     const float* __restrict__ conv_b, const float* __restrict__ fc1_w,
     const float* __restrict__ fc1_b, const float* __restrict__ fc2_w,
     const float* __restrict__ fc2_b, float* __restrict__ out)
{
    __shared__ __align__(16) float sb[8448];   // 33.8 KB, aliased per phase
    const int tid  = threadIdx.x;
    const int lane = tid & 31;
    const int wp   = tid >> 5;

    // ================= phase 0: trig tables, vrmax reset, fc0 =================
    for (int t = blockIdx.x*NTHR + tid; t < SN*MODES; t += GRID*NTHR) {
        int j = t >> 4, k = t & 15;
        int ph = (j * k) & (SN - 1);
        double ang = (double)ph * (6.283185307179586476925286766559 / (double)SN);
        g_cos[t] = (float)cos(ang);
        g_sin[t] = (float)sin(ang);
    }
    for (int t = blockIdx.x*NTHR + tid; t < 4*BS; t += GRID*NTHR) g_vrmax[t] = 0;
    for (int e = blockIdx.x*NTHR + tid; e < BS*W*SN; e += GRID*NTHR) {
        int bb = e / (W*SN);
        int r  = e - bb*(W*SN);
        int c  = r >> 9;
        int j  = r & (SN-1);
        float x0 = x[(bb*SN + j)*2 + 0];
        float x1 = x[(bb*SN + j)*2 + 1];
        g_h[e] = x0*fc0_w[c] + x1*fc0_w[W + c] + fc0_b[c];
    }
    gbar();

    for (int l = 0; l < 4; l++) {
        // ===== Phase A: DFT (0..127) + 1x1 conv (128..255) =====
        for (int task = blockIdx.x; task < 256; task += GRID) {
            if (task < 128) {
                int bc = task;
                for (int e = tid; e < SN; e += NTHR) sb[e] = g_h[bc*SN + e];
                __syncthreads();
                int m0 = wp, m1 = wp + 8;
                float re0=0.f, im0=0.f, re1=0.f, im1=0.f;
                for (int j = lane; j < SN; j += 32) {
                    float hv = sb[j];
                    re0 += hv * g_cos[j*MODES + m0]; im0 -= hv * g_sin[j*MODES + m0];
                    re1 += hv * g_cos[j*MODES + m1]; im1 -= hv * g_sin[j*MODES + m1];
                }
                #pragma unroll
                for (int o = 16; o; o >>= 1) {
                    re0 += __shfl_down_sync(0xffffffffu, re0, o);
                    im0 += __shfl_down_sync(0xffffffffu, im0, o);
                    re1 += __shfl_down_sync(0xffffffffu, re1, o);
                    im1 += __shfl_down_sync(0xffffffffu, im1, o);
                }
                if (lane == 0) {
                    g_Xf[(bc*MODES + m0)*2 + 0] = re0;
                    g_Xf[(bc*MODES + m0)*2 + 1] = im0;
                    g_Xf[(bc*MODES + m1)*2 + 0] = re1;
                    g_Xf[(bc*MODES + m1)*2 + 1] = im1;
                }
                __syncthreads();
            } else {
                int t2 = task - 128;
                int b = t2 >> 6, o = t2 & 63;
                if (tid < W) sb[tid] = conv_w[((size_t)l*W + o)*W + tid];
                __syncthreads();
                float bias = conv_b[l*W + o];
                for (int j = tid; j < SN; j += NTHR) {
                    float acc = bias;
                    #pragma unroll 16
                    for (int c = 0; c < W; c++) acc += sb[c] * g_h[(b*W + c)*SN + j];
                    g_p [(b*W + o)*SN + j] = acc;
                    g_pT[((size_t)b*SN + j)*W + o] = acc;
                }
                __syncthreads();
            }
        }
        gbar();

        // ===== Phase B: mix+synth (0..127) || ux distance tiles (128..255) =====
        {
            const float2* wl2 = (const float2*)(spec_w + (size_t)l*W*W*MODES*2);
            for (int task = blockIdx.x; task < 256; task += GRID) {
                if (task < 128) {
                    int b = task >> 6, o = task & 63;
                    for (int e = tid; e < W*MODES*2; e += NTHR) sb[e] = g_Xf[b*W*MODES*2 + e];
                    __syncthreads();
                    int k0 = wp, k1 = wp + 8;
                    float yr0=0.f, yi0=0.f, yr1=0.f, yi1=0.f;
                    for (int i = lane; i < W; i += 32) {
                        float2 w0 = wl2[(i*W + o)*MODES + k0];
                        float2 w1 = wl2[(i*W + o)*MODES + k1];
                        float xr0 = sb[(i*MODES + k0)*2], xi0 = sb[(i*MODES + k0)*2 + 1];
                        float xr1 = sb[(i*MODES + k1)*2], xi1 = sb[(i*MODES + k1)*2 + 1];
                        yr0 += xr0*w0.x - xi0*w0.y;  yi0 += xr0*w0.y + xi0*w0.x;
                        yr1 += xr1*w1.x - xi1*w1.y;  yi1 += xr1*w1.y + xi1*w1.x;
                    }
                    #pragma unroll
                    for (int o2 = 16; o2; o2 >>= 1) {
                        yr0 += __shfl_down_sync(0xffffffffu, yr0, o2);
                        yi0 += __shfl_down_sync(0xffffffffu, yi0, o2);
                        yr1 += __shfl_down_sync(0xffffffffu, yr1, o2);
                        yi1 += __shfl_down_sync(0xffffffffu, yi1, o2);
                    }
                    if (lane == 0) {
                        sb[2048 + k0*2] = yr0; sb[2048 + k0*2 + 1] = yi0;
                        sb[2048 + k1*2] = yr1; sb[2048 + k1*2 + 1] = yi1;
                    }
                    __syncthreads();
                    for (int j = tid; j < SN; j += NTHR) {
                        float acc = sb[2048];
                        #pragma unroll
                        for (int k = 1; k < MODES; k++)
                            acc += 2.f*(sb[2048 + 2*k]*g_cos[j*MODES + k]
                                      - sb[2048 + 2*k + 1]*g_sin[j*MODES + k]);
                        float a = acc * (1.0f/(float)SN);
                        g_a [(b*W + o)*SN + j] = a;
                        g_aT[((size_t)b*SN + j)*W + o] = a;
                    }
                    __syncthreads();
                } else {
                    int t2 = task - 128;
                    dist_tile<0>(g_p, g_ux, t2 >> 6, t2 & 63, sb, l);
                }
            }
        }
        gbar();

        // ===== Phase C: vr tiles from a (+ vrmax), 128 tasks =====
        for (int task = blockIdx.x; task < 128; task += GRID)
            dist_tile<1>(g_a, g_vr, task >> 6, task & 63, sb, l);
        gbar();

        // ===== Phase E1: dense masked GEMM tiles (0..127) || vecs gather rows (128..1151) =====
        for (int task = blockIdx.x; task < 128 + BS*SN; task += GRID) {
            __syncthreads();
            if (task < 128) {
                // dense Mx/Mv partial tile: b, j-tile(64), i-chunk(64)
                int b = task >> 6, r6 = task & 63;
                int jt = r6 >> 3, ch = r6 & 7;
                float* sp = sb;
                float* sa = sb + 4096;
                unsigned* smk = (unsigned*)(sb + 8192);   // 128 mask words
                const float4* pT4 = (const float4*)(g_pT + ((size_t)b*SN + ch*64)*W);
                const float4* aT4 = (const float4*)(g_aT + ((size_t)b*SN + ch*64)*W);
                for (int e = tid; e < 1024; e += NTHR) {
                    ((float4*)sp)[e] = pT4[e];
                    ((float4*)sa)[e] = aT4[e];
                }
                float thr = 0.1f * __int_as_float(g_vrmax[l*BS + b]);
                for (int r = 0; r < 16; r++) {
                    int e = r*256 + tid;
                    int il = e >> 6, jl = e & 63;
                    size_t off = ((size_t)b*SN + ch*64 + il)*SN + jt*64 + jl;
                    unsigned m = __ballot_sync(0xffffffffu, g_vr[off]*g_ux[off] > thr);
                    if (lane == 0) smk[e >> 5] = m;
                }
                __syncthreads();
                int tx = tid & 15, ty = tid >> 4;
                int sh = (tx*4) & 31, wsel = tx >> 3;
                float ax[4][4] = {}, av[4][4] = {};
                for (int i = 0; i < 64; i++) {
                    unsigned mw = smk[i*2 + wsel];
                    float4 pv = *(float4*)(sp + i*64 + ty*4);
                    float4 aq = *(float4*)(sa + i*64 + ty*4);
                    #pragma unroll
                    for (int s = 0; s < 4; s++) {
                        if ((mw >> (sh + s)) & 1u) {
                            ax[s][0] += pv.x; ax[s][1] += pv.y; ax[s][2] += pv.z; ax[s][3] += pv.w;
                            av[s][0] += aq.x; av[s][1] += aq.y; av[s][2] += aq.z; av[s][3] += aq.w;
                        }
                    }
                }
                #pragma unroll
                for (int s = 0; s < 4; s++) {
                    int j = jt*64 + tx*4 + s;
                    size_t o = (((size_t)b*SN + j)*8 + ch)*W + ty*4;
                    *(float4*)(g_Mx + o) = make_float4(ax[s][0], ax[s][1], ax[s][2], ax[s][3]);
                    *(float4*)(g_Mv + o) = make_float4(av[s][0], av[s][1], av[s][2], av[s][3]);
                }
            } else {
                // gather row: vecs projection sum only
                int t2 = task - 128;
                int b = t2 >> 9, j = t2 & 511;
                int*   s_pid = (int*)sb;
                float* s_wt  = sb + 512;
                int*   s_cnt = (int*)(sb + 1024);
                float* sR    = sb + 1056;
                float thr = 0.1f * __int_as_float(g_vrmax[l*BS + b]);
                const float* vrrow = g_vr + ((size_t)b*SN + j)*SN;
                const float* uxrow = g_ux + ((size_t)b*SN + j)*SN;
                // warp-local ordered list build (segment = 64 i's per warp)
                int cl = 0;
                #pragma unroll
                for (int it = 0; it < 2; it++) {
                    int i = wp*64 + it*32 + lane;
                    float vr = vrrow[i];
                    bool pred = (vr * uxrow[i]) > thr;
                    unsigned m = __ballot_sync(0xffffffffu, pred);
                    if (pred) {
                        int pos = wp*64 + cl + __popc(m & ((1u << lane) - 1u));
                        int lo = i < j ? i : j, hi = i < j ? j : i;
                        s_pid[pos] = lo*SN - (lo*(lo+1))/2 + hi - lo - 1;
                        s_wt [pos] = (i < j) ? vr : -vr;
                    }
                    cl += __popc(m);
                }
                if (lane == 0) s_cnt[wp] = cl;
                __syncthreads();
                int c = tid & 63, g4 = tid >> 6;
                float rr = 0.f;
                int ntot = 0;
                const float* vb = vecs + (((size_t)l*BS + b)*W + c)*(size_t)PAIRS;
                #pragma unroll
                for (int s = 0; s < 8; s++) {
                    int ns = s_cnt[s];
                    ntot += ns;
                    int base = s*64;
                    for (int k = g4; k < ns; k += 16) {
                        int p4[4]; float w4[4]; int m4 = 0;
                        #pragma unroll
                        for (int u = 0; u < 4; u++) {
                            int kk = k + 4*u;
                            if (kk < ns) { p4[m4] = s_pid[base+kk]; w4[m4] = s_wt[base+kk]; m4++; }
                        }
                        float rv[4];
                        #pragma unroll
                        for (int u = 0; u < 4; u++) if (u < m4) rv[u] = vb[p4[u]];
                        #pragma unroll
                        for (int u = 0; u < 4; u++) if (u < m4) rr += w4[u]*rv[u];
                    }
                }
                sR[tid] = rr;
                __syncthreads();
                if (tid < 64)
                    g_R[((size_t)b*SN + j)*W + tid] = sR[tid] + sR[tid+64] + sR[tid+128] + sR[tid+192];
                if (tid == 0) g_N[b*SN + j] = ntot;
            }
        }
        gbar();

        // ===== Phase E2: elementwise finalize =====
        {
            int relu = (l < 3);
            for (int e = blockIdx.x*NTHR + tid; e < BS*SN*W; e += GRID*NTHR) {
                int c = e & 63;
                int row = e >> 6;            // b*SN + j
                int b = row >> 9, j = row & 511;
                const float* mxp = g_Mx + ((size_t)row*8)*W + c;
                const float* mvp = g_Mv + ((size_t)row*8)*W + c;
                float Mx = 0.f, Mv = 0.f;
                #pragma unroll
                for (int ch = 0; ch < 8; ch++) { Mx += mxp[ch*W]; Mv += mvp[ch*W]; }
                float R  = g_R[(size_t)row*W + c];
                float nf = (float)g_N[row];
                float aj = g_aT[(size_t)row*W + c];
                float pj = g_pT[(size_t)row*W + c];
                float vnew = aj + 0.5f*aj*nf - 0.5f*Mv + R;
                float C = nf + 1.0f;
                float xnew = (Mx + pj + pj*C) / (2.0f*C);
                float h = xnew + vnew;
                if (relu) h = fmaxf(h, 0.0f);
                g_h [(b*W + c)*SN + j] = h;
                g_hT[(size_t)row*W + c] = h;
            }
        }
        gbar();
    }

    // ================= head: relu(h@fc1+b1)@fc2+b2 =================
    for (int task = blockIdx.x; task < 512; task += GRID) {
        int b = task >> 8, sp = task & 255;
        int half = tid >> 7, m = tid & 127;
        int s = sp*2 + half;
        __syncthreads();
        if (tid < 128) {
            int hh = tid >> 6, i = tid & 63;
            sb[tid] = g_hT[((size_t)b*SN + (sp*2 + hh))*W + i];
        }
        __syncthreads();
        float acc = fc1_b[m];
        #pragma unroll 16
        for (int cc = 0; cc < W; cc++) acc += sb[half*64 + cc] * fc1_w[cc*128 + m];
        acc = fmaxf(acc, 0.0f) * fc2_w[m];
        sb[128 + tid] = acc;
        __syncthreads();
        #pragma unroll
        for (int o2 = 64; o2; o2 >>= 1) {
            if (m < o2) sb[128 + half*128 + m] += sb[128 + half*128 + m + o2];
            __syncthreads();
        }
        if (m == 0) out[b*SN + s] = sb[128 + half*128] + fc2_b[0];
    }
}

// ---------------- launch ----------------
extern "C" void kernel_launch(void* const* d_in, const int* in_sizes, int n_in,
                              void* d_out, int out_size) {
    const float* x      = (const float*)d_in[0];
    const float* vecs   = (const float*)d_in[2];
    const float* fc0_w  = (const float*)d_in[3];
    const float* fc0_b  = (const float*)d_in[4];
    const float* spec_w = (const float*)d_in[5];
    const float* conv_w = (const float*)d_in[6];
    const float* conv_b = (const float*)d_in[7];
    const float* fc1_w  = (const float*)d_in[8];
    const float* fc1_b  = (const float*)d_in[9];
    const float* fc2_w  = (const float*)d_in[10];
    const float* fc2_b  = (const float*)d_in[11];
    float* out = (float*)d_out;

    mega<<<GRID, NTHR>>>(x, vecs, fc0_w, fc0_b, spec_w, conv_w, conv_b,
                         fc1_w, fc1_b, fc2_w, fc2_b, out);
}